// round 4
// baseline (speedup 1.0000x reference)
#include <cuda_runtime.h>

#define B_ 8
#define C_ 384
#define L_ 1024
#define H_ 6
#define D_ 64
#define NW_ 9   // 2*window+1

// Scratch (allocation-free rule: device globals)
__device__ float g_q[B_*C_*L_];
__device__ float g_k[B_*C_*L_];
__device__ float g_v[B_*C_*L_];
__device__ float g_res[B_*C_*L_];

// ---------------------------------------------------------------------------
// Projection GEMM: Y[b][o][l] = sum_c W[o][c] * X[b][c][l] + bias[o]
// 64x64 tiles, ktile=16, 4x4 microtile, float4 everywhere.
// ---------------------------------------------------------------------------
__global__ __launch_bounds__(256) void proj_kernel(const float* __restrict__ W,
                                                   const float* __restrict__ bias,
                                                   const float* __restrict__ X,
                                                   float* __restrict__ Y) {
    __shared__ float WsT[16][68];   // [c][o]  (transposed at load)
    __shared__ float Xs[16][68];    // [c][l]
    const int b  = blockIdx.z;
    const int o0 = blockIdx.y * 64;
    const int l0 = blockIdx.x * 64;
    const int tid = threadIdx.x;           // 0..255
    const int tx = tid & 15, ty = tid >> 4;
    const float* Xb = X + (size_t)b * C_ * L_;

    float acc[4][4];
#pragma unroll
    for (int r = 0; r < 4; r++)
#pragma unroll
        for (int c = 0; c < 4; c++) acc[r][c] = 0.f;

    // W load mapping: i = o index, kkb = c sub-block
    const int wi  = tid >> 2;          // 0..63
    const int kkb = (tid & 3) * 4;     // 0,4,8,12
    // X load mapping
    const int xk = tid >> 4;           // 0..15
    const int xj = (tid & 15) * 4;     // 0..60

    for (int c0 = 0; c0 < C_; c0 += 16) {
        float4 w4 = *(const float4*)(W + (size_t)(o0 + wi) * C_ + c0 + kkb);
        float4 x4 = *(const float4*)(Xb + (size_t)(c0 + xk) * L_ + l0 + xj);
        WsT[kkb + 0][wi] = w4.x;
        WsT[kkb + 1][wi] = w4.y;
        WsT[kkb + 2][wi] = w4.z;
        WsT[kkb + 3][wi] = w4.w;
        *(float4*)&Xs[xk][xj] = x4;
        __syncthreads();
#pragma unroll
        for (int kk = 0; kk < 16; kk++) {
            float4 a4 = *(const float4*)&WsT[kk][ty * 4];
            float4 b4 = *(const float4*)&Xs[kk][tx * 4];
            float a[4] = {a4.x, a4.y, a4.z, a4.w};
            float bb[4] = {b4.x, b4.y, b4.z, b4.w};
#pragma unroll
            for (int r = 0; r < 4; r++)
#pragma unroll
                for (int c = 0; c < 4; c++) acc[r][c] += a[r] * bb[c];
        }
        __syncthreads();
    }

#pragma unroll
    for (int r = 0; r < 4; r++) {
        int o = o0 + ty * 4 + r;
        float bv = bias[o];
        float4 out4 = make_float4(acc[r][0] + bv, acc[r][1] + bv,
                                  acc[r][2] + bv, acc[r][3] + bv);
        *(float4*)(Y + (size_t)b * C_ * L_ + (size_t)o * L_ + l0 + tx * 4) = out4;
    }
}

// ---------------------------------------------------------------------------
// Flash attention with 9-wide relative band.
//   score[i][j] = (q_i.k_j + [|j-i|<=4] q_i.Ek[j-i+4]) * scale
//   res[i]      = sum_j p_ij * v_j + sum_{|d|<=4} p[i,i+d] * Ev[d+4]
// Block: 64 query rows for one (b,h). 256 threads (16x16), 4x4 microtiles,
// K-tiles of 64. Dynamic smem (~74KB).
// ---------------------------------------------------------------------------
__global__ __launch_bounds__(256, 2) void attn_kernel(const float* __restrict__ erk,
                                                      const float* __restrict__ erv) {
    extern __shared__ float sm[];
    float (*Qt)[68]  = (float(*)[68])(sm);            // [dim][qpos]   64x68
    float (*Kt)[68]  = (float(*)[68])(sm + 4352);     // [dim][kpos]   64x68
    float (*Vt)[65]  = (float(*)[65])(sm + 8704);     // [dim][kpos]   64x65 (odd pad)
    float (*Ps)[68]  = (float(*)[68])(sm + 12864);    // [qpos][kpos]  64x68
    float (*Eks)[64] = (float(*)[64])(sm + 17216);    // [delta][dim]
    float (*Evs)[64] = (float(*)[64])(sm + 17792);
    float (*qEk)[NW_] = (float(*)[NW_])(sm + 18368);  // [qrow][delta]

    const int tid = threadIdx.x;
    const int tx = tid & 15, ty = tid >> 4;
    const int i0 = blockIdx.x * 64;
    const int bh = blockIdx.y;
    const int b = bh / H_, h = bh % H_;

    const float* Qg = g_q + (size_t)(b * C_ + h * D_) * L_;
    const float* Kg = g_k + (size_t)(b * C_ + h * D_) * L_;
    const float* Vg = g_v + (size_t)(b * C_ + h * D_) * L_;

    // Load Q tile (float4 coalesced) + embedding tables
#pragma unroll
    for (int it = 0; it < 4; it++) {
        int g = tid + it * 256;
        int r = g >> 4, i4 = (g & 15) * 4;
        float4 q4 = *(const float4*)(Qg + (size_t)r * L_ + i0 + i4);
        *(float4*)&Qt[r][i4] = q4;
    }
    for (int e = tid; e < NW_ * 64; e += 256) {
        int dd = e >> 6, r = e & 63;
        Eks[dd][r] = erk[(h * NW_ + dd) * 64 + r];
        Evs[dd][r] = erv[(h * NW_ + dd) * 64 + r];
    }
    __syncthreads();

    // qEk[i][dd] = q_i . Ek[dd]
    for (int idx = tid; idx < 64 * NW_; idx += 256) {
        int dd = idx >> 6, i = idx & 63;
        float s = 0.f;
#pragma unroll
        for (int r = 0; r < 64; r++) s += Qt[r][i] * Eks[dd][r];
        qEk[i][dd] = s;
    }
    // visibility: first sync inside the tile loop fences qEk

    float m_i[4], l_i[4], Oacc[4][4];
#pragma unroll
    for (int ii = 0; ii < 4; ii++) {
        m_i[ii] = -1e30f; l_i[ii] = 0.f;
#pragma unroll
        for (int rr = 0; rr < 4; rr++) Oacc[ii][rr] = 0.f;
    }

    const float scale = 0.125f;  // 1/sqrt(64)

    for (int j0 = 0; j0 < L_; j0 += 64) {
        __syncthreads();  // prev tile's PV reads of Kt/Vt done; fences qEk (iter 0)
        // Load K,V tiles (float4 coalesced); V stored with odd pad (scalar stores)
#pragma unroll
        for (int it = 0; it < 4; it++) {
            int g = tid + it * 256;
            int r = g >> 4, j4 = (g & 15) * 4;
            float4 k4 = *(const float4*)(Kg + (size_t)r * L_ + j0 + j4);
            *(float4*)&Kt[r][j4] = k4;
            float4 v4 = *(const float4*)(Vg + (size_t)r * L_ + j0 + j4);
            Vt[r][j4 + 0] = v4.x;
            Vt[r][j4 + 1] = v4.y;
            Vt[r][j4 + 2] = v4.z;
            Vt[r][j4 + 3] = v4.w;
        }
        __syncthreads();

        // S = Q.K^T : rows ty*4+ii, cols tx*4+jj
        float S[4][4];
#pragma unroll
        for (int ii = 0; ii < 4; ii++)
#pragma unroll
            for (int jj = 0; jj < 4; jj++) S[ii][jj] = 0.f;
#pragma unroll 16
        for (int r = 0; r < 64; r++) {
            float4 q4 = *(const float4*)&Qt[r][ty * 4];
            float4 k4 = *(const float4*)&Kt[r][tx * 4];
            float a[4] = {q4.x, q4.y, q4.z, q4.w};
            float bb[4] = {k4.x, k4.y, k4.z, k4.w};
#pragma unroll
            for (int ii = 0; ii < 4; ii++)
#pragma unroll
                for (int jj = 0; jj < 4; jj++) S[ii][jj] += a[ii] * bb[jj];
        }

        // Relative-K band bias + scale
#pragma unroll
        for (int ii = 0; ii < 4; ii++) {
            int qi = i0 + ty * 4 + ii;
#pragma unroll
            for (int jj = 0; jj < 4; jj++) {
                int kj = j0 + tx * 4 + jj;
                int d = kj - qi;
                float bias = (d >= -4 && d <= 4) ? qEk[ty * 4 + ii][d + 4] : 0.f;
                S[ii][jj] = (S[ii][jj] + bias) * scale;
            }
        }

        // Online softmax: each row's 64 cols live in 16 lanes (fixed ty within
        // half-warp), xor-shuffles 8,4,2,1 reduce across tx.
        float alpha[4];
#pragma unroll
        for (int ii = 0; ii < 4; ii++) {
            float tm = fmaxf(fmaxf(S[ii][0], S[ii][1]), fmaxf(S[ii][2], S[ii][3]));
#pragma unroll
            for (int o = 8; o >= 1; o >>= 1)
                tm = fmaxf(tm, __shfl_xor_sync(0xffffffffu, tm, o));
            float mnew = fmaxf(m_i[ii], tm);
            float ts = 0.f;
#pragma unroll
            for (int jj = 0; jj < 4; jj++) {
                S[ii][jj] = __expf(S[ii][jj] - mnew);
                ts += S[ii][jj];
            }
#pragma unroll
            for (int o = 8; o >= 1; o >>= 1)
                ts += __shfl_xor_sync(0xffffffffu, ts, o);
            float a2 = __expf(m_i[ii] - mnew);
            alpha[ii] = a2;
            l_i[ii] = l_i[ii] * a2 + ts;
            m_i[ii] = mnew;
        }
#pragma unroll
        for (int ii = 0; ii < 4; ii++)
#pragma unroll
            for (int rr = 0; rr < 4; rr++) Oacc[ii][rr] *= alpha[ii];

        // Stage P (row qi is produced and consumed by the same half-warp)
#pragma unroll
        for (int ii = 0; ii < 4; ii++)
            *(float4*)&Ps[ty * 4 + ii][tx * 4] =
                make_float4(S[ii][0], S[ii][1], S[ii][2], S[ii][3]);
        __syncwarp();

        // O += P.V : rows ty*4+ii, dims tx*4+rr
#pragma unroll 8
        for (int j = 0; j < 64; j++) {
            float p[4], vv[4];
#pragma unroll
            for (int ii = 0; ii < 4; ii++) p[ii] = Ps[ty * 4 + ii][j];   // broadcast
#pragma unroll
            for (int rr = 0; rr < 4; rr++) vv[rr] = Vt[tx * 4 + rr][j];  // conflict-free (pad 65)
#pragma unroll
            for (int ii = 0; ii < 4; ii++)
#pragma unroll
                for (int rr = 0; rr < 4; rr++) Oacc[ii][rr] += p[ii] * vv[rr];
        }

        // Relative-V band: O[i] += p[i, i+d] * Ev[d+4] for in-tile columns.
        if (j0 + 63 >= i0 - 4 && j0 <= i0 + 67) {
#pragma unroll
            for (int ii = 0; ii < 4; ii++) {
                int qi = i0 + ty * 4 + ii;
#pragma unroll
                for (int dd = 0; dd < NW_; dd++) {
                    int j = qi + dd - 4 - j0;
                    if (j >= 0 && j < 64) {
                        float pv = Ps[ty * 4 + ii][j];
#pragma unroll
                        for (int rr = 0; rr < 4; rr++)
                            Oacc[ii][rr] += pv * Evs[dd][tx * 4 + rr];
                    }
                }
            }
        }
    }
    __syncthreads();

    // Epilogue: normalize, stage transposed in Qt, coalesced store.
    float* Rg = g_res + (size_t)(b * C_ + h * D_) * L_;
#pragma unroll
    for (int ii = 0; ii < 4; ii++) {
        float inv = 1.0f / l_i[ii];
#pragma unroll
        for (int rr = 0; rr < 4; rr++)
            Qt[tx * 4 + rr][ty * 4 + ii] = Oacc[ii][rr] * inv;
    }
    __syncthreads();
#pragma unroll
    for (int it = 0; it < 4; it++) {
        int g = tid + it * 256;
        int r = g >> 4, i4 = (g & 15) * 4;
        float4 o4 = *(const float4*)&Qt[r][i4];
        *(float4*)(Rg + (size_t)r * L_ + i0 + i4) = o4;
    }
}

// ---------------------------------------------------------------------------
extern "C" void kernel_launch(void* const* d_in, const int* in_sizes, int n_in,
                              void* d_out, int out_size) {
    const float* x   = (const float*)d_in[0];
    const float* wq  = (const float*)d_in[1];
    const float* bq  = (const float*)d_in[2];
    const float* wk  = (const float*)d_in[3];
    const float* bk  = (const float*)d_in[4];
    const float* wv  = (const float*)d_in[5];
    const float* bv  = (const float*)d_in[6];
    const float* wo  = (const float*)d_in[7];
    const float* bo  = (const float*)d_in[8];
    const float* erk = (const float*)d_in[9];
    const float* erv = (const float*)d_in[10];
    float* out = (float*)d_out;

    float *gq, *gk, *gv, *gres;
    cudaGetSymbolAddress((void**)&gq,   g_q);
    cudaGetSymbolAddress((void**)&gk,   g_k);
    cudaGetSymbolAddress((void**)&gv,   g_v);
    cudaGetSymbolAddress((void**)&gres, g_res);

    const int attn_smem = 18944 * 4;  // 75776 bytes
    cudaFuncSetAttribute(attn_kernel, cudaFuncAttributeMaxDynamicSharedMemorySize,
                         attn_smem);

    dim3 pgrid(L_ / 64, C_ / 64, B_);  // (16, 6, 8)
    proj_kernel<<<pgrid, 256>>>(wq, bq, x, gq);
    proj_kernel<<<pgrid, 256>>>(wk, bk, x, gk);
    proj_kernel<<<pgrid, 256>>>(wv, bv, x, gv);

    dim3 agrid(L_ / 64, B_ * H_);      // (16, 48)
    attn_kernel<<<agrid, 256, attn_smem>>>(erk, erv);

    proj_kernel<<<pgrid, 256>>>(wo, bo, gres, out);
}

// round 6
// speedup vs baseline: 1.2151x; 1.2151x over previous
#include <cuda_runtime.h>
#include <cstdint>

#define B_ 8
#define C_ 384
#define L_ 1024
#define H_ 6
#define D_ 64
#define NW_ 9   // 2*window+1

// Scratch (allocation-free rule: device globals)
__device__ float g_q[B_*C_*L_];
__device__ float g_k[B_*C_*L_];
__device__ float g_v[B_*C_*L_];
__device__ float g_xT[B_*L_*C_];    // x transposed: [b][l][c]
__device__ float g_resT[B_*L_*C_];  // attn result transposed: [b][l][c]

__device__ __forceinline__ uint32_t f2tf32(float f) {
    uint32_t r;
    asm("cvt.rna.tf32.f32 %0, %1;" : "=r"(r) : "f"(f));
    return r;
}

__device__ __forceinline__ void mma_tf32(float* d, const uint32_t* a,
                                         uint32_t b0, uint32_t b1) {
    asm volatile("mma.sync.aligned.m16n8k8.row.col.f32.tf32.tf32.f32 "
                 "{%0,%1,%2,%3}, {%4,%5,%6,%7}, {%8,%9}, {%0,%1,%2,%3};"
                 : "+f"(d[0]), "+f"(d[1]), "+f"(d[2]), "+f"(d[3])
                 : "r"(a[0]), "r"(a[1]), "r"(a[2]), "r"(a[3]),
                   "r"(b0), "r"(b1));
}

// ===========================================================================
// Transpose: dst[b][col][row] = src[b][row][col].  rows=C_, cols=L_.
// ===========================================================================
__global__ __launch_bounds__(256) void transpose_kernel(const float* __restrict__ src,
                                                        float* __restrict__ dst,
                                                        int rows, int cols) {
    __shared__ float tile[32][33];
    const int b = blockIdx.z;
    const int r0 = blockIdx.y * 32;
    const int c0 = blockIdx.x * 32;
    const int tx = threadIdx.x & 31, ty = threadIdx.x >> 5;
    const float* sb = src + (size_t)b * rows * cols;
    float* db = dst + (size_t)b * rows * cols;
#pragma unroll
    for (int i = 0; i < 4; i++)
        tile[ty + i * 8][tx] = sb[(size_t)(r0 + ty + i * 8) * cols + c0 + tx];
    __syncthreads();
#pragma unroll
    for (int i = 0; i < 4; i++)
        db[(size_t)(c0 + ty + i * 8) * rows + r0 + tx] = tile[tx][ty + i * 8];
}

// ===========================================================================
// tf32 projection GEMM via mma.sync.m16n8k8 (target-generic PTX).
//   Y[b][o][l] = sum_c W[o][c] * XT[b][l][c] + bias[o]
// A=W row-major (MxK), B=XT as col-major KxN (storage [n][k]) => row.col.
// Block tile 128(o) x 128(l), K-tile 32. 8 warps = 4(M) x 2(N),
// warp tile 32x64 = 2x8 mma tiles.
// ===========================================================================
__global__ __launch_bounds__(256) void proj_mma(const float* __restrict__ W,
                                                const float* __restrict__ bias,
                                                const float* __restrict__ XT,
                                                float* __restrict__ Y) {
    __shared__ float As[128][36];   // [o][k] tf32 bits, pad 36 (144B rows, 16B-aligned)
    __shared__ float Bs[128][36];   // [l][k] tf32 bits
    const int tid = threadIdx.x;
    const int wid = tid >> 5, lane = tid & 31;
    const int g = lane >> 2, tig = lane & 3;      // groupID / thread-in-group
    const int warpM = wid & 3, warpN = wid >> 2;  // 4 x 2 warp grid
    const int b  = blockIdx.z;
    const int o0 = blockIdx.y * 128;
    const int l0 = blockIdx.x * 128;

    float acc[2][8][4];
#pragma unroll
    for (int mt = 0; mt < 2; mt++)
#pragma unroll
        for (int nt = 0; nt < 8; nt++)
#pragma unroll
            for (int i = 0; i < 4; i++) acc[mt][nt][i] = 0.f;

    for (int ct = 0; ct < C_ / 32; ct++) {
        const int c0 = ct * 32;
        // Stage A (W) and B (XT): 128 rows x 32 k-floats each; float4 loads,
        // rna-round to tf32 at store.
#pragma unroll
        for (int it = 0; it < 4; it++) {
            int idx = it * 256 + tid;
            int row = idx >> 3, c4 = (idx & 7) * 4;
            float4 w4 = *(const float4*)(W + (size_t)(o0 + row) * C_ + c0 + c4);
            uint4 wt = make_uint4(f2tf32(w4.x), f2tf32(w4.y), f2tf32(w4.z), f2tf32(w4.w));
            *(uint4*)&As[row][c4] = wt;
            float4 x4 = *(const float4*)(XT + ((size_t)b * L_ + l0 + row) * C_ + c0 + c4);
            uint4 xt = make_uint4(f2tf32(x4.x), f2tf32(x4.y), f2tf32(x4.z), f2tf32(x4.w));
            *(uint4*)&Bs[row][c4] = xt;
        }
        __syncthreads();

#pragma unroll
        for (int ks = 0; ks < 4; ks++) {
            const int k0 = ks * 8;
            uint32_t a[2][4];
#pragma unroll
            for (int mt = 0; mt < 2; mt++) {
                int rb = warpM * 32 + mt * 16;
                a[mt][0] = __float_as_uint(As[rb + g][k0 + tig]);
                a[mt][1] = __float_as_uint(As[rb + g + 8][k0 + tig]);
                a[mt][2] = __float_as_uint(As[rb + g][k0 + tig + 4]);
                a[mt][3] = __float_as_uint(As[rb + g + 8][k0 + tig + 4]);
            }
#pragma unroll
            for (int nt = 0; nt < 8; nt++) {
                int nb = warpN * 64 + nt * 8;
                uint32_t b0 = __float_as_uint(Bs[nb + g][k0 + tig]);
                uint32_t b1 = __float_as_uint(Bs[nb + g][k0 + tig + 4]);
#pragma unroll
                for (int mt = 0; mt < 2; mt++)
                    mma_tf32(acc[mt][nt], a[mt], b0, b1);
            }
        }
        __syncthreads();
    }

    // Epilogue: D fragment (c0:(g,2t) c1:(g,2t+1) c2:(g+8,2t) c3:(g+8,2t+1))
#pragma unroll
    for (int mt = 0; mt < 2; mt++) {
        int r0 = o0 + warpM * 32 + mt * 16;
        float bv0 = bias[r0 + g];
        float bv1 = bias[r0 + g + 8];
        float* y0 = Y + ((size_t)b * C_ + r0 + g) * L_;
        float* y1 = Y + ((size_t)b * C_ + r0 + g + 8) * L_;
#pragma unroll
        for (int nt = 0; nt < 8; nt++) {
            int col = l0 + warpN * 64 + nt * 8 + 2 * tig;
            *(float2*)(y0 + col) = make_float2(acc[mt][nt][0] + bv0, acc[mt][nt][1] + bv0);
            *(float2*)(y1 + col) = make_float2(acc[mt][nt][2] + bv1, acc[mt][nt][3] + bv1);
        }
    }
}

// ===========================================================================
// Flash attention with 9-wide relative band (fp32 CUDA cores).
// Writes result TRANSPOSED to g_resT[b][l][c] for the O-projection.
// ===========================================================================
__global__ __launch_bounds__(256, 2) void attn_kernel(const float* __restrict__ erk,
                                                      const float* __restrict__ erv) {
    extern __shared__ float sm[];
    float (*Qt)[68]  = (float(*)[68])(sm);            // [dim][qpos]   64x68
    float (*Kt)[68]  = (float(*)[68])(sm + 4352);     // [dim][kpos]   64x68
    float (*Vt)[65]  = (float(*)[65])(sm + 8704);     // [dim][kpos]   64x65
    float (*Ps)[68]  = (float(*)[68])(sm + 12864);    // [qpos][kpos]  64x68
    float (*Eks)[64] = (float(*)[64])(sm + 17216);
    float (*Evs)[64] = (float(*)[64])(sm + 17792);
    float (*qEk)[NW_] = (float(*)[NW_])(sm + 18368);

    const int tid = threadIdx.x;
    const int tx = tid & 15, ty = tid >> 4;
    const int i0 = blockIdx.x * 64;
    const int bh = blockIdx.y;
    const int b = bh / H_, h = bh % H_;

    const float* Qg = g_q + (size_t)(b * C_ + h * D_) * L_;
    const float* Kg = g_k + (size_t)(b * C_ + h * D_) * L_;
    const float* Vg = g_v + (size_t)(b * C_ + h * D_) * L_;

#pragma unroll
    for (int it = 0; it < 4; it++) {
        int g = tid + it * 256;
        int r = g >> 4, i4 = (g & 15) * 4;
        *(float4*)&Qt[r][i4] = *(const float4*)(Qg + (size_t)r * L_ + i0 + i4);
    }
    for (int e = tid; e < NW_ * 64; e += 256) {
        int dd = e >> 6, r = e & 63;
        Eks[dd][r] = erk[(h * NW_ + dd) * 64 + r];
        Evs[dd][r] = erv[(h * NW_ + dd) * 64 + r];
    }
    __syncthreads();

    for (int idx = tid; idx < 64 * NW_; idx += 256) {
        int dd = idx >> 6, i = idx & 63;
        float s = 0.f;
#pragma unroll
        for (int r = 0; r < 64; r++) s += Qt[r][i] * Eks[dd][r];
        qEk[i][dd] = s;
    }

    float m_i[4], l_i[4], Oacc[4][4];
#pragma unroll
    for (int ii = 0; ii < 4; ii++) {
        m_i[ii] = -1e30f; l_i[ii] = 0.f;
#pragma unroll
        for (int rr = 0; rr < 4; rr++) Oacc[ii][rr] = 0.f;
    }

    const float scale = 0.125f;

    for (int j0 = 0; j0 < L_; j0 += 64) {
        __syncthreads();
#pragma unroll
        for (int it = 0; it < 4; it++) {
            int g = tid + it * 256;
            int r = g >> 4, j4 = (g & 15) * 4;
            *(float4*)&Kt[r][j4] = *(const float4*)(Kg + (size_t)r * L_ + j0 + j4);
            float4 v4 = *(const float4*)(Vg + (size_t)r * L_ + j0 + j4);
            Vt[r][j4 + 0] = v4.x; Vt[r][j4 + 1] = v4.y;
            Vt[r][j4 + 2] = v4.z; Vt[r][j4 + 3] = v4.w;
        }
        __syncthreads();

        float S[4][4];
#pragma unroll
        for (int ii = 0; ii < 4; ii++)
#pragma unroll
            for (int jj = 0; jj < 4; jj++) S[ii][jj] = 0.f;
#pragma unroll 16
        for (int r = 0; r < 64; r++) {
            float4 q4 = *(const float4*)&Qt[r][ty * 4];
            float4 k4 = *(const float4*)&Kt[r][tx * 4];
            float a[4] = {q4.x, q4.y, q4.z, q4.w};
            float bb[4] = {k4.x, k4.y, k4.z, k4.w};
#pragma unroll
            for (int ii = 0; ii < 4; ii++)
#pragma unroll
                for (int jj = 0; jj < 4; jj++) S[ii][jj] += a[ii] * bb[jj];
        }

#pragma unroll
        for (int ii = 0; ii < 4; ii++) {
            int qi = i0 + ty * 4 + ii;
#pragma unroll
            for (int jj = 0; jj < 4; jj++) {
                int kj = j0 + tx * 4 + jj;
                int d = kj - qi;
                float bias = (d >= -4 && d <= 4) ? qEk[ty * 4 + ii][d + 4] : 0.f;
                S[ii][jj] = (S[ii][jj] + bias) * scale;
            }
        }

        float alpha[4];
#pragma unroll
        for (int ii = 0; ii < 4; ii++) {
            float tm = fmaxf(fmaxf(S[ii][0], S[ii][1]), fmaxf(S[ii][2], S[ii][3]));
#pragma unroll
            for (int o = 8; o >= 1; o >>= 1)
                tm = fmaxf(tm, __shfl_xor_sync(0xffffffffu, tm, o));
            float mnew = fmaxf(m_i[ii], tm);
            float ts = 0.f;
#pragma unroll
            for (int jj = 0; jj < 4; jj++) {
                S[ii][jj] = __expf(S[ii][jj] - mnew);
                ts += S[ii][jj];
            }
#pragma unroll
            for (int o = 8; o >= 1; o >>= 1)
                ts += __shfl_xor_sync(0xffffffffu, ts, o);
            float a2 = __expf(m_i[ii] - mnew);
            alpha[ii] = a2;
            l_i[ii] = l_i[ii] * a2 + ts;
            m_i[ii] = mnew;
        }
#pragma unroll
        for (int ii = 0; ii < 4; ii++)
#pragma unroll
            for (int rr = 0; rr < 4; rr++) Oacc[ii][rr] *= alpha[ii];

#pragma unroll
        for (int ii = 0; ii < 4; ii++)
            *(float4*)&Ps[ty * 4 + ii][tx * 4] =
                make_float4(S[ii][0], S[ii][1], S[ii][2], S[ii][3]);
        __syncwarp();

#pragma unroll 8
        for (int j = 0; j < 64; j++) {
            float p[4], vv[4];
#pragma unroll
            for (int ii = 0; ii < 4; ii++) p[ii] = Ps[ty * 4 + ii][j];
#pragma unroll
            for (int rr = 0; rr < 4; rr++) vv[rr] = Vt[tx * 4 + rr][j];
#pragma unroll
            for (int ii = 0; ii < 4; ii++)
#pragma unroll
                for (int rr = 0; rr < 4; rr++) Oacc[ii][rr] += p[ii] * vv[rr];
        }

        if (j0 + 63 >= i0 - 4 && j0 <= i0 + 67) {
#pragma unroll
            for (int ii = 0; ii < 4; ii++) {
                int qi = i0 + ty * 4 + ii;
#pragma unroll
                for (int dd = 0; dd < NW_; dd++) {
                    int j = qi + dd - 4 - j0;
                    if (j >= 0 && j < 64) {
                        float pv = Ps[ty * 4 + ii][j];
#pragma unroll
                        for (int rr = 0; rr < 4; rr++)
                            Oacc[ii][rr] += pv * Evs[dd][tx * 4 + rr];
                    }
                }
            }
        }
    }

    // Epilogue: write TRANSPOSED result resT[b][l][h*64 + dim] (coalesced f4).
#pragma unroll
    for (int ii = 0; ii < 4; ii++) {
        float inv = 1.0f / l_i[ii];
        float4 o4 = make_float4(Oacc[ii][0] * inv, Oacc[ii][1] * inv,
                                Oacc[ii][2] * inv, Oacc[ii][3] * inv);
        *(float4*)(g_resT + ((size_t)b * L_ + i0 + ty * 4 + ii) * C_ + h * D_ + tx * 4) = o4;
    }
}

// ---------------------------------------------------------------------------
extern "C" void kernel_launch(void* const* d_in, const int* in_sizes, int n_in,
                              void* d_out, int out_size) {
    const float* x   = (const float*)d_in[0];
    const float* wq  = (const float*)d_in[1];
    const float* bq  = (const float*)d_in[2];
    const float* wk  = (const float*)d_in[3];
    const float* bk  = (const float*)d_in[4];
    const float* wv  = (const float*)d_in[5];
    const float* bv  = (const float*)d_in[6];
    const float* wo  = (const float*)d_in[7];
    const float* bo  = (const float*)d_in[8];
    const float* erk = (const float*)d_in[9];
    const float* erv = (const float*)d_in[10];
    float* out = (float*)d_out;

    float *gq, *gk, *gv, *gxT, *gresT;
    cudaGetSymbolAddress((void**)&gq,    g_q);
    cudaGetSymbolAddress((void**)&gk,    g_k);
    cudaGetSymbolAddress((void**)&gv,    g_v);
    cudaGetSymbolAddress((void**)&gxT,   g_xT);
    cudaGetSymbolAddress((void**)&gresT, g_resT);

    const int attn_smem = 18944 * 4;  // 75776 bytes
    cudaFuncSetAttribute(attn_kernel, cudaFuncAttributeMaxDynamicSharedMemorySize,
                         attn_smem);

    // x[b][c][l] -> xT[b][l][c]
    dim3 tgrid(L_ / 32, C_ / 32, B_);   // (32, 12, 8)
    transpose_kernel<<<tgrid, 256>>>(x, gxT, C_, L_);

    dim3 pgrid(L_ / 128, C_ / 128, B_);  // (8, 3, 8)
    proj_mma<<<pgrid, 256>>>(wq, bq, gxT, gq);
    proj_mma<<<pgrid, 256>>>(wk, bk, gxT, gk);
    proj_mma<<<pgrid, 256>>>(wv, bv, gxT, gv);

    dim3 agrid(L_ / 64, B_ * H_);       // (16, 48)
    attn_kernel<<<agrid, 256, attn_smem>>>(erk, erv);

    proj_mma<<<pgrid, 256>>>(wo, bo, gresT, out);
}

// round 7
// speedup vs baseline: 2.5576x; 2.1048x over previous
#include <cuda_runtime.h>
#include <cstdint>

#define B_ 8
#define C_ 384
#define L_ 1024
#define H_ 6
#define D_ 64
#define NW_ 9   // 2*window+1

// Scratch (allocation-free rule: device globals). All [b][l][c] layout.
__device__ float g_qT[B_*L_*C_];
__device__ float g_kT[B_*L_*C_];
__device__ float g_vT[B_*L_*C_];
__device__ float g_xT[B_*L_*C_];
__device__ float g_resT[B_*L_*C_];

__device__ __forceinline__ uint32_t f2tf32(float f) {
    uint32_t r;
    asm("cvt.rna.tf32.f32 %0, %1;" : "=r"(r) : "f"(f));
    return r;
}

__device__ __forceinline__ void mma_tf32(float* d, const uint32_t* a,
                                         uint32_t b0, uint32_t b1) {
    asm volatile("mma.sync.aligned.m16n8k8.row.col.f32.tf32.tf32.f32 "
                 "{%0,%1,%2,%3}, {%4,%5,%6,%7}, {%8,%9}, {%0,%1,%2,%3};"
                 : "+f"(d[0]), "+f"(d[1]), "+f"(d[2]), "+f"(d[3])
                 : "r"(a[0]), "r"(a[1]), "r"(a[2]), "r"(a[3]),
                   "r"(b0), "r"(b1));
}

// ===========================================================================
// Transpose: dst[b][col][row] = src[b][row][col].  rows=C_, cols=L_.
// ===========================================================================
__global__ __launch_bounds__(256) void transpose_kernel(const float* __restrict__ src,
                                                        float* __restrict__ dst,
                                                        int rows, int cols) {
    __shared__ float tile[32][33];
    const int b = blockIdx.z;
    const int r0 = blockIdx.y * 32;
    const int c0 = blockIdx.x * 32;
    const int tx = threadIdx.x & 31, ty = threadIdx.x >> 5;
    const float* sb = src + (size_t)b * rows * cols;
    float* db = dst + (size_t)b * rows * cols;
#pragma unroll
    for (int i = 0; i < 4; i++)
        tile[ty + i * 8][tx] = sb[(size_t)(r0 + ty + i * 8) * cols + c0 + tx];
    __syncthreads();
#pragma unroll
    for (int i = 0; i < 4; i++)
        db[(size_t)(c0 + ty + i * 8) * rows + r0 + tx] = tile[tx][ty + i * 8];
}

// ===========================================================================
// Fused QKV projection, TRANSPOSED output:
//   Y[b][l][o] = sum_c XT[b][l][c] * W[o][c] + bias[o]
// D[m=l][n=o]; A = XT (row-major MxK), B = W ([n][k] => col.col) -> row.col.
// grid.z = b*3 + pid (pid selects q/k/v). Output rna-rounded to tf32.
// ===========================================================================
__global__ __launch_bounds__(256) void qkv_mma(const float* __restrict__ wq,
                                               const float* __restrict__ bq,
                                               const float* __restrict__ wk,
                                               const float* __restrict__ bk,
                                               const float* __restrict__ wv,
                                               const float* __restrict__ bv,
                                               const float* __restrict__ XT,
                                               float* __restrict__ q,
                                               float* __restrict__ k,
                                               float* __restrict__ v) {
    __shared__ float As[128][36];   // XT tile [l][c]
    __shared__ float Bs[128][36];   // W  tile [o][c]
    const int tid = threadIdx.x;
    const int wid = tid >> 5, lane = tid & 31;
    const int g = lane >> 2, tig = lane & 3;
    const int warpM = wid & 3, warpN = wid >> 2;
    const int pid = blockIdx.z % 3;
    const int b   = blockIdx.z / 3;
    const int l0  = blockIdx.y * 128;
    const int o0  = blockIdx.x * 128;

    const float* W    = (pid == 0) ? wq : (pid == 1) ? wk : wv;
    const float* bias = (pid == 0) ? bq : (pid == 1) ? bk : bv;
    float* Y          = (pid == 0) ? q  : (pid == 1) ? k  : v;

    float acc[2][8][4];
#pragma unroll
    for (int mt = 0; mt < 2; mt++)
#pragma unroll
        for (int nt = 0; nt < 8; nt++)
#pragma unroll
            for (int i = 0; i < 4; i++) acc[mt][nt][i] = 0.f;

    for (int ct = 0; ct < C_ / 32; ct++) {
        const int c0 = ct * 32;
#pragma unroll
        for (int it = 0; it < 4; it++) {
            int idx = it * 256 + tid;
            int row = idx >> 3, c4 = (idx & 7) * 4;
            float4 x4 = *(const float4*)(XT + ((size_t)b * L_ + l0 + row) * C_ + c0 + c4);
            uint4 xt = make_uint4(f2tf32(x4.x), f2tf32(x4.y), f2tf32(x4.z), f2tf32(x4.w));
            *(uint4*)&As[row][c4] = xt;
            float4 w4 = *(const float4*)(W + (size_t)(o0 + row) * C_ + c0 + c4);
            uint4 wt = make_uint4(f2tf32(w4.x), f2tf32(w4.y), f2tf32(w4.z), f2tf32(w4.w));
            *(uint4*)&Bs[row][c4] = wt;
        }
        __syncthreads();
#pragma unroll
        for (int ks = 0; ks < 4; ks++) {
            const int k0 = ks * 8;
            uint32_t a[2][4];
#pragma unroll
            for (int mt = 0; mt < 2; mt++) {
                int rb = warpM * 32 + mt * 16;
                a[mt][0] = __float_as_uint(As[rb + g][k0 + tig]);
                a[mt][1] = __float_as_uint(As[rb + g + 8][k0 + tig]);
                a[mt][2] = __float_as_uint(As[rb + g][k0 + tig + 4]);
                a[mt][3] = __float_as_uint(As[rb + g + 8][k0 + tig + 4]);
            }
#pragma unroll
            for (int nt = 0; nt < 8; nt++) {
                int nb = warpN * 64 + nt * 8;
                uint32_t b0 = __float_as_uint(Bs[nb + g][k0 + tig]);
                uint32_t b1 = __float_as_uint(Bs[nb + g][k0 + tig + 4]);
#pragma unroll
                for (int mt = 0; mt < 2; mt++)
                    mma_tf32(acc[mt][nt], a[mt], b0, b1);
            }
        }
        __syncthreads();
    }

    // Epilogue: rows = l, cols = o. Store rna(tf32) so attn stages raw bits.
#pragma unroll
    for (int mt = 0; mt < 2; mt++) {
        int lr0 = l0 + warpM * 32 + mt * 16;
        float* y0 = Y + ((size_t)b * L_ + lr0 + g) * C_;
        float* y1 = Y + ((size_t)b * L_ + lr0 + g + 8) * C_;
#pragma unroll
        for (int nt = 0; nt < 8; nt++) {
            int col = o0 + warpN * 64 + nt * 8 + 2 * tig;
            float bv0 = bias[col], bv1 = bias[col + 1];
            float2 r0 = make_float2(__uint_as_float(f2tf32(acc[mt][nt][0] + bv0)),
                                    __uint_as_float(f2tf32(acc[mt][nt][1] + bv1)));
            float2 r1 = make_float2(__uint_as_float(f2tf32(acc[mt][nt][2] + bv0)),
                                    __uint_as_float(f2tf32(acc[mt][nt][3] + bv1)));
            *(float2*)(y0 + col) = r0;
            *(float2*)(y1 + col) = r1;
        }
    }
}

// ===========================================================================
// O projection (R6-proven): out[b][o][l] = sum_c W[o][c]*resT[b][l][c] + bias
// ===========================================================================
__global__ __launch_bounds__(256) void proj_mma(const float* __restrict__ W,
                                                const float* __restrict__ bias,
                                                const float* __restrict__ XT,
                                                float* __restrict__ Y) {
    __shared__ float As[128][36];
    __shared__ float Bs[128][36];
    const int tid = threadIdx.x;
    const int wid = tid >> 5, lane = tid & 31;
    const int g = lane >> 2, tig = lane & 3;
    const int warpM = wid & 3, warpN = wid >> 2;
    const int b  = blockIdx.z;
    const int o0 = blockIdx.y * 128;
    const int l0 = blockIdx.x * 128;

    float acc[2][8][4];
#pragma unroll
    for (int mt = 0; mt < 2; mt++)
#pragma unroll
        for (int nt = 0; nt < 8; nt++)
#pragma unroll
            for (int i = 0; i < 4; i++) acc[mt][nt][i] = 0.f;

    for (int ct = 0; ct < C_ / 32; ct++) {
        const int c0 = ct * 32;
#pragma unroll
        for (int it = 0; it < 4; it++) {
            int idx = it * 256 + tid;
            int row = idx >> 3, c4 = (idx & 7) * 4;
            float4 w4 = *(const float4*)(W + (size_t)(o0 + row) * C_ + c0 + c4);
            uint4 wt = make_uint4(f2tf32(w4.x), f2tf32(w4.y), f2tf32(w4.z), f2tf32(w4.w));
            *(uint4*)&As[row][c4] = wt;
            float4 x4 = *(const float4*)(XT + ((size_t)b * L_ + l0 + row) * C_ + c0 + c4);
            uint4 xt = make_uint4(f2tf32(x4.x), f2tf32(x4.y), f2tf32(x4.z), f2tf32(x4.w));
            *(uint4*)&Bs[row][c4] = xt;
        }
        __syncthreads();
#pragma unroll
        for (int ks = 0; ks < 4; ks++) {
            const int k0 = ks * 8;
            uint32_t a[2][4];
#pragma unroll
            for (int mt = 0; mt < 2; mt++) {
                int rb = warpM * 32 + mt * 16;
                a[mt][0] = __float_as_uint(As[rb + g][k0 + tig]);
                a[mt][1] = __float_as_uint(As[rb + g + 8][k0 + tig]);
                a[mt][2] = __float_as_uint(As[rb + g][k0 + tig + 4]);
                a[mt][3] = __float_as_uint(As[rb + g + 8][k0 + tig + 4]);
            }
#pragma unroll
            for (int nt = 0; nt < 8; nt++) {
                int nb = warpN * 64 + nt * 8;
                uint32_t b0 = __float_as_uint(Bs[nb + g][k0 + tig]);
                uint32_t b1 = __float_as_uint(Bs[nb + g][k0 + tig + 4]);
#pragma unroll
                for (int mt = 0; mt < 2; mt++)
                    mma_tf32(acc[mt][nt], a[mt], b0, b1);
            }
        }
        __syncthreads();
    }

#pragma unroll
    for (int mt = 0; mt < 2; mt++) {
        int r0 = o0 + warpM * 32 + mt * 16;
        float bv0 = bias[r0 + g];
        float bv1 = bias[r0 + g + 8];
        float* y0 = Y + ((size_t)b * C_ + r0 + g) * L_;
        float* y1 = Y + ((size_t)b * C_ + r0 + g + 8) * L_;
#pragma unroll
        for (int nt = 0; nt < 8; nt++) {
            int col = l0 + warpN * 64 + nt * 8 + 2 * tig;
            *(float2*)(y0 + col) = make_float2(acc[mt][nt][0] + bv0, acc[mt][nt][1] + bv0);
            *(float2*)(y1 + col) = make_float2(acc[mt][nt][2] + bv1, acc[mt][nt][3] + bv1);
        }
    }
}

// ===========================================================================
// Tensor-core flash attention with 9-wide relative band.
// Block: 64 q-rows of one (b,h); 4 warps x 32 = 128 thr; warp = 16 rows.
// QK^T and PV via m16n8k8 tf32. Softmax on CUDA cores (4-lane reductions).
// Q pre-scaled by 1/8 at load. Smem stride 72 => conflict-free fragments.
// ===========================================================================
#define AP 72
__global__ __launch_bounds__(128) void attn_mma(const float* __restrict__ erk,
                                                const float* __restrict__ erv) {
    extern __shared__ float sm[];
    float* Qs  = sm;           // [64][72]
    float* Ks  = sm + 4608;    // [64][72]  (rows = kpos, cols = dim)
    float* Vs  = sm + 9216;    // [64][72]  (rows = kpos, cols = dim)
    float* Ps  = sm + 13824;   // [64][72]  (rows = qpos, cols = kpos)
    float* Eks = sm + 18432;   // [9][64]
    float* Evs = sm + 19008;   // [9][64]
    float* qEk = sm + 19584;   // [64][12]

    const int tid = threadIdx.x;
    const int w = tid >> 5, lane = tid & 31;
    const int g = lane >> 2, tig = lane & 3;
    const int rb = w * 16;
    const int i0 = blockIdx.x * 64;
    const int bh = blockIdx.y;
    const int b = bh / H_, h = bh % H_;

    const float* QT = g_qT + (size_t)b * L_ * C_ + h * D_;
    const float* KT = g_kT + (size_t)b * L_ * C_ + h * D_;
    const float* VT = g_vT + (size_t)b * L_ * C_ + h * D_;

    // Q tile, pre-scaled by 1/8 (values already tf32-rounded by qkv epilogue;
    // *0.125 is exact — power of two).
#pragma unroll
    for (int it = 0; it < 8; it++) {
        int idx = it * 128 + tid;
        int r = idx >> 4, d4 = (idx & 15) * 4;
        float4 q4 = *(const float4*)(QT + (size_t)(i0 + r) * C_ + d4);
        Qs[r * AP + d4 + 0] = q4.x * 0.125f;
        Qs[r * AP + d4 + 1] = q4.y * 0.125f;
        Qs[r * AP + d4 + 2] = q4.z * 0.125f;
        Qs[r * AP + d4 + 3] = q4.w * 0.125f;
    }
    for (int e = tid; e < NW_ * 64; e += 128) {
        int dd = e >> 6, r = e & 63;
        Eks[dd * 64 + r] = erk[(h * NW_ + dd) * 64 + r];
        Evs[dd * 64 + r] = erv[(h * NW_ + dd) * 64 + r];
    }
    __syncthreads();

    // qEk[i][dd] = (q_i/8) . Ek[dd]   (scale folded in)
    for (int e = tid; e < 64 * NW_; e += 128) {
        int dd = e >> 6, i = e & 63;
        float s = 0.f;
#pragma unroll
        for (int d = 0; d < 64; d++) s += Qs[i * AP + d] * Eks[dd * 64 + d];
        qEk[i * 12 + dd] = s;
    }

    float m0 = -1e30f, m1 = -1e30f, l0 = 0.f, l1 = 0.f;
    float o[8][4];
#pragma unroll
    for (int nt = 0; nt < 8; nt++)
#pragma unroll
        for (int i = 0; i < 4; i++) o[nt][i] = 0.f;

    const int qi0 = i0 + rb + g;
    const int qi1 = qi0 + 8;

    for (int j0 = 0; j0 < L_; j0 += 64) {
        __syncthreads();  // prior tile's reads done; also fences qEk (iter 0)
#pragma unroll
        for (int it = 0; it < 8; it++) {
            int idx = it * 128 + tid;
            int r = idx >> 4, d4 = (idx & 15) * 4;
            *(float4*)&Ks[r * AP + d4] = *(const float4*)(KT + (size_t)(j0 + r) * C_ + d4);
            *(float4*)&Vs[r * AP + d4] = *(const float4*)(VT + (size_t)(j0 + r) * C_ + d4);
        }
        __syncthreads();

        // S = (Q/8) K^T : warp rows [rb, rb+16), cols 64 (8 n-tiles)
        float s[8][4];
#pragma unroll
        for (int nt = 0; nt < 8; nt++)
#pragma unroll
            for (int i = 0; i < 4; i++) s[nt][i] = 0.f;
#pragma unroll
        for (int ks = 0; ks < 8; ks++) {
            const int k0 = ks * 8;
            uint32_t a[4];
            a[0] = __float_as_uint(Qs[(rb + g) * AP + k0 + tig]);
            a[1] = __float_as_uint(Qs[(rb + g + 8) * AP + k0 + tig]);
            a[2] = __float_as_uint(Qs[(rb + g) * AP + k0 + tig + 4]);
            a[3] = __float_as_uint(Qs[(rb + g + 8) * AP + k0 + tig + 4]);
#pragma unroll
            for (int nt = 0; nt < 8; nt++) {
                uint32_t b0 = __float_as_uint(Ks[(nt * 8 + g) * AP + k0 + tig]);
                uint32_t b1 = __float_as_uint(Ks[(nt * 8 + g) * AP + k0 + tig + 4]);
                mma_tf32(s[nt], a, b0, b1);
            }
        }

        // Relative-K band bias (qEk already carries the 1/8 scale)
        const bool near = (j0 == i0) || (j0 + 64 == i0) || (j0 == i0 + 64);
        if (near) {
#pragma unroll
            for (int nt = 0; nt < 8; nt++) {
#pragma unroll
                for (int c = 0; c < 2; c++) {
                    int j = j0 + nt * 8 + 2 * tig + c;
                    int d0 = j - qi0;
                    if (d0 >= -4 && d0 <= 4) s[nt][c] += qEk[(rb + g) * 12 + d0 + 4];
                    int d1 = j - qi1;
                    if (d1 >= -4 && d1 <= 4) s[nt][c + 2] += qEk[(rb + g + 8) * 12 + d1 + 4];
                }
            }
        }

        // Online softmax, rows qi0 (s[..][0..1]) and qi1 (s[..][2..3]).
        float tm0 = -1e30f, tm1 = -1e30f;
#pragma unroll
        for (int nt = 0; nt < 8; nt++) {
            tm0 = fmaxf(tm0, fmaxf(s[nt][0], s[nt][1]));
            tm1 = fmaxf(tm1, fmaxf(s[nt][2], s[nt][3]));
        }
#pragma unroll
        for (int off = 1; off <= 2; off <<= 1) {
            tm0 = fmaxf(tm0, __shfl_xor_sync(0xffffffffu, tm0, off));
            tm1 = fmaxf(tm1, __shfl_xor_sync(0xffffffffu, tm1, off));
        }
        float mn0 = fmaxf(m0, tm0), mn1 = fmaxf(m1, tm1);
        float ts0 = 0.f, ts1 = 0.f;
#pragma unroll
        for (int nt = 0; nt < 8; nt++) {
            s[nt][0] = __expf(s[nt][0] - mn0);
            s[nt][1] = __expf(s[nt][1] - mn0);
            s[nt][2] = __expf(s[nt][2] - mn1);
            s[nt][3] = __expf(s[nt][3] - mn1);
            ts0 += s[nt][0] + s[nt][1];
            ts1 += s[nt][2] + s[nt][3];
        }
#pragma unroll
        for (int off = 1; off <= 2; off <<= 1) {
            ts0 += __shfl_xor_sync(0xffffffffu, ts0, off);
            ts1 += __shfl_xor_sync(0xffffffffu, ts1, off);
        }
        float al0 = __expf(m0 - mn0), al1 = __expf(m1 - mn1);
        l0 = l0 * al0 + ts0;  m0 = mn0;
        l1 = l1 * al1 + ts1;  m1 = mn1;
#pragma unroll
        for (int nt = 0; nt < 8; nt++) {
            o[nt][0] *= al0; o[nt][1] *= al0;
            o[nt][2] *= al1; o[nt][3] *= al1;
        }

        // Stage P (tf32-rounded). Rows belong to this warp only.
#pragma unroll
        for (int nt = 0; nt < 8; nt++) {
            int col = nt * 8 + 2 * tig;
            *(float2*)&Ps[(rb + g) * AP + col] =
                make_float2(__uint_as_float(f2tf32(s[nt][0])),
                            __uint_as_float(f2tf32(s[nt][1])));
            *(float2*)&Ps[(rb + g + 8) * AP + col] =
                make_float2(__uint_as_float(f2tf32(s[nt][2])),
                            __uint_as_float(f2tf32(s[nt][3])));
        }
        __syncwarp();

        // O += P V : A = Ps [q][kpos], B = Vs [kpos][dim] (B elem (k,n)=Vs[k][n])
#pragma unroll
        for (int ks = 0; ks < 8; ks++) {
            const int k0 = ks * 8;
            uint32_t a[4];
            a[0] = __float_as_uint(Ps[(rb + g) * AP + k0 + tig]);
            a[1] = __float_as_uint(Ps[(rb + g + 8) * AP + k0 + tig]);
            a[2] = __float_as_uint(Ps[(rb + g) * AP + k0 + tig + 4]);
            a[3] = __float_as_uint(Ps[(rb + g + 8) * AP + k0 + tig + 4]);
#pragma unroll
            for (int nt = 0; nt < 8; nt++) {
                uint32_t b0 = __float_as_uint(Vs[(k0 + tig) * AP + nt * 8 + g]);
                uint32_t b1 = __float_as_uint(Vs[(k0 + tig + 4) * AP + nt * 8 + g]);
                mma_tf32(o[nt], a, b0, b1);
            }
        }

        // Relative-V band: O[i][n] += p[i, i+d] * Ev[d][n]
        if (near) {
#pragma unroll
            for (int dd = 0; dd < NW_; dd++) {
                int j0r = qi0 + dd - 4 - j0;
                if (j0r >= 0 && j0r < 64) {
                    float p = Ps[(rb + g) * AP + j0r];
#pragma unroll
                    for (int nt = 0; nt < 8; nt++) {
                        int col = nt * 8 + 2 * tig;
                        o[nt][0] += p * Evs[dd * 64 + col];
                        o[nt][1] += p * Evs[dd * 64 + col + 1];
                    }
                }
                int j1r = qi1 + dd - 4 - j0;
                if (j1r >= 0 && j1r < 64) {
                    float p = Ps[(rb + g + 8) * AP + j1r];
#pragma unroll
                    for (int nt = 0; nt < 8; nt++) {
                        int col = nt * 8 + 2 * tig;
                        o[nt][2] += p * Evs[dd * 64 + col];
                        o[nt][3] += p * Evs[dd * 64 + col + 1];
                    }
                }
            }
        }
    }

    // Epilogue: normalize, store resT[b][l][h*64+dim].
    float inv0 = 1.0f / l0, inv1 = 1.0f / l1;
    float* r0p = g_resT + ((size_t)b * L_ + qi0) * C_ + h * D_;
    float* r1p = g_resT + ((size_t)b * L_ + qi1) * C_ + h * D_;
#pragma unroll
    for (int nt = 0; nt < 8; nt++) {
        int col = nt * 8 + 2 * tig;
        *(float2*)(r0p + col) = make_float2(o[nt][0] * inv0, o[nt][1] * inv0);
        *(float2*)(r1p + col) = make_float2(o[nt][2] * inv1, o[nt][3] * inv1);
    }
}

// ---------------------------------------------------------------------------
extern "C" void kernel_launch(void* const* d_in, const int* in_sizes, int n_in,
                              void* d_out, int out_size) {
    const float* x   = (const float*)d_in[0];
    const float* wq  = (const float*)d_in[1];
    const float* bq  = (const float*)d_in[2];
    const float* wk  = (const float*)d_in[3];
    const float* bk  = (const float*)d_in[4];
    const float* wv  = (const float*)d_in[5];
    const float* bv  = (const float*)d_in[6];
    const float* wo  = (const float*)d_in[7];
    const float* bo  = (const float*)d_in[8];
    const float* erk = (const float*)d_in[9];
    const float* erv = (const float*)d_in[10];
    float* out = (float*)d_out;

    float *gqT, *gkT, *gvT, *gxT, *gresT;
    cudaGetSymbolAddress((void**)&gqT,   g_qT);
    cudaGetSymbolAddress((void**)&gkT,   g_kT);
    cudaGetSymbolAddress((void**)&gvT,   g_vT);
    cudaGetSymbolAddress((void**)&gxT,   g_xT);
    cudaGetSymbolAddress((void**)&gresT, g_resT);

    const int attn_smem = 20352 * 4;  // 81408 bytes
    cudaFuncSetAttribute(attn_mma, cudaFuncAttributeMaxDynamicSharedMemorySize,
                         attn_smem);

    // x[b][c][l] -> xT[b][l][c]
    dim3 tgrid(L_ / 32, C_ / 32, B_);
    transpose_kernel<<<tgrid, 256>>>(x, gxT, C_, L_);

    // Fused QKV, transposed tf32 outputs
    dim3 qgrid(C_ / 128, L_ / 128, B_ * 3);   // (3, 8, 24)
    qkv_mma<<<qgrid, 256>>>(wq, bq, wk, bk, wv, bv, gxT, gqT, gkT, gvT);

    // Tensor-core attention
    dim3 agrid(L_ / 64, B_ * H_);             // (16, 48)
    attn_mma<<<agrid, 128, attn_smem>>>(erk, erv);

    // O projection
    dim3 ogrid(L_ / 128, C_ / 128, B_);       // (8, 3, 8)
    proj_mma<<<ogrid, 256>>>(wo, bo, gresT, out);
}